// round 4
// baseline (speedup 1.0000x reference)
#include <cuda_runtime.h>
#include <cstdint>

#define NN 50000
#define DD 128
#define EE 800000

// Scratch (allocation-free rule)
__device__ float g_fj[NN * DD];
__device__ float g_a1[NN];
__device__ float g_a2[NN];

// ---------------------------------------------------------------------------
// m16n8k8 tf32 mma (sm_80+ baseline PTX; HMMA path on sm_103)
// Fragment layout (g=lane/4, t=lane%4), verified vs cutlass SM80 TN traits:
//   A {a0..a3} = (row g, k t), (g+8, t), (g, t+4), (g+8, t+4)
//   B {b0,b1}  = (k t, n g), (k t+4, n g)
//   C {c0..c3} = (g, 2t), (g, 2t+1), (g+8, 2t), (g+8, 2t+1)
// ---------------------------------------------------------------------------
__device__ __forceinline__ void mma_tf32(float* c, const uint32_t* a,
                                         uint32_t b0, uint32_t b1) {
    asm volatile(
        "mma.sync.aligned.m16n8k8.row.col.f32.tf32.tf32.f32 "
        "{%0,%1,%2,%3}, {%4,%5,%6,%7}, {%8,%9}, {%0,%1,%2,%3};"
        : "+f"(c[0]), "+f"(c[1]), "+f"(c[2]), "+f"(c[3])
        : "r"(a[0]), "r"(a[1]), "r"(a[2]), "r"(a[3]), "r"(b0), "r"(b1));
}

// SMEM float offsets
#define SAS 132                 // sA stride: [128][132]
#define SBS 132                 // sB stride: [256][132]
#define EPS 264                 // epilogue buffer stride: [128][264]
#define OFF_B   (128 * SAS)     // 16896
#define OFF_PAR (OFF_B + 256 * SBS)   // 50688 : b1|b2|wa1|wa2 (512 floats)
#define OFF_A1  (OFF_PAR + 512)       // 51200 : float[128]
#define OFF_A2  (OFF_A1 + 128)        // 51328
#define SM_FLOATS (OFF_A2 + 128)      // 51456 -> 205824 bytes
#define SM_BYTES (SM_FLOATS * 4)

// ---------------------------------------------------------------------------
// Kernel 1: tf32 tensor-core GEMM + fused GAT epilogue.
//   D[128x256] = X_tile[128x128] @ [W1;W2]^T
//   fi = relu(D[:, :128]+b1), fj = relu(D[:,128:]+b2)
//   a1 = fi.wa1+ba1, a2 = fj.wa2+ba2
//   out = fi + sigmoid(a1+a2)*fj  (self-loop folded);  stash fj, a1, a2.
// 512 threads / 16 warps; warp tile 32 rows x 64 cols (2 x 8 m16n8k8 tiles).
// ---------------------------------------------------------------------------
__global__ __launch_bounds__(512, 1) void gat_gemm(
    const float* __restrict__ X,
    const float* __restrict__ W1, const float* __restrict__ b1,
    const float* __restrict__ W2, const float* __restrict__ b2,
    const float* __restrict__ wa1, const float* __restrict__ ba1,
    const float* __restrict__ wa2, const float* __restrict__ ba2,
    float* __restrict__ out)
{
    extern __shared__ float sm[];
    float* sA  = sm;            // [128][132]
    float* sB  = sm + OFF_B;    // [256][132]  rows = output cols n, cols = k
    float* par = sm + OFF_PAR;  // b1[128] b2[128] wa1[128] wa2[128]
    float* sA1 = sm + OFF_A1;
    float* sA2 = sm + OFF_A2;

    const int tid  = threadIdx.x;
    const int warp = tid >> 5;
    const int lane = tid & 31;
    const int g    = lane >> 2;   // groupID
    const int t    = lane & 3;    // threadID_in_group
    const int block_row = blockIdx.x * 128;

    if (tid < 128) {
        par[tid]       = b1[tid];
        par[128 + tid] = b2[tid];
        par[256 + tid] = wa1[tid];
        par[384 + tid] = wa2[tid];
        sA1[tid] = 0.f;
        sA2[tid] = 0.f;
    }

    // Stage A (X tile)
    for (int i = tid; i < 128 * 32; i += 512) {
        int r = i >> 5, c4 = i & 31;
        float4 v = make_float4(0.f, 0.f, 0.f, 0.f);
        if (block_row + r < NN) v = ((const float4*)X)[(block_row + r) * 32 + c4];
        *(float4*)(sA + r * SAS + c4 * 4) = v;
    }
    // Stage B ([W1;W2] row-major = [n][k], exactly mma's col-B layout)
    for (int i = tid; i < 256 * 32; i += 512) {
        int n = i >> 5, c4 = i & 31;
        float4 v = (n < 128) ? ((const float4*)W1)[n * 32 + c4]
                             : ((const float4*)W2)[(n - 128) * 32 + c4];
        *(float4*)(sB + n * SBS + c4 * 4) = v;
    }
    __syncthreads();

    const int wr = warp & 3;    // row group (x32 rows)
    const int wc = warp >> 2;   // col group (x64 cols)

    float c[2][8][4];
    #pragma unroll
    for (int rt = 0; rt < 2; rt++)
        #pragma unroll
        for (int ct = 0; ct < 8; ct++)
            #pragma unroll
            for (int i = 0; i < 4; i++) c[rt][ct][i] = 0.f;

    const float* Ab = sA + (wr * 32 + g) * SAS;
    const float* Bb = sB + (wc * 64 + g) * SBS;

    #pragma unroll
    for (int ks = 0; ks < 16; ks++) {
        const int k0 = ks * 8 + t;
        uint32_t a[2][4];
        #pragma unroll
        for (int rt = 0; rt < 2; rt++) {
            const float* ap = Ab + rt * 16 * SAS;
            a[rt][0] = __float_as_uint(ap[k0]);
            a[rt][1] = __float_as_uint(ap[8 * SAS + k0]);
            a[rt][2] = __float_as_uint(ap[k0 + 4]);
            a[rt][3] = __float_as_uint(ap[8 * SAS + k0 + 4]);
        }
        #pragma unroll
        for (int ct = 0; ct < 8; ct++) {
            const float* bp = Bb + ct * 8 * SBS;
            uint32_t b0 = __float_as_uint(bp[k0]);
            uint32_t b1r = __float_as_uint(bp[k0 + 4]);
            mma_tf32(c[0][ct], a[0], b0, b1r);
            mma_tf32(c[1][ct], a[1], b0, b1r);
        }
    }
    __syncthreads();   // all warps done reading sA/sB; safe to reuse as EP

    // Bias + ReLU in regs; partial a-dots; write fi/fj to exchange buffer.
    float* EP = sm;    // [128][264]; cols 0..127 = fi, 128..255 = fj
    const int colbase = wc * 64;
    float pa[2][2] = {{0.f, 0.f}, {0.f, 0.f}};   // [rt][row half]

    #pragma unroll
    for (int ct = 0; ct < 8; ct++) {
        const int col = colbase + ct * 8 + 2 * t;   // global col (0..255)
        const float w0 = par[256 + col], w1 = par[257 + col];
        const float bb0 = par[col], bb1 = par[col + 1];
        #pragma unroll
        for (int rt = 0; rt < 2; rt++) {
            float f0 = fmaxf(c[rt][ct][0] + bb0, 0.f);
            float f1 = fmaxf(c[rt][ct][1] + bb1, 0.f);
            float f2 = fmaxf(c[rt][ct][2] + bb0, 0.f);
            float f3 = fmaxf(c[rt][ct][3] + bb1, 0.f);
            pa[rt][0] += f0 * w0 + f1 * w1;
            pa[rt][1] += f2 * w0 + f3 * w1;
            int r0 = wr * 32 + rt * 16 + g;
            *(float2*)(EP + r0 * EPS + col)       = make_float2(f0, f1);
            *(float2*)(EP + (r0 + 8) * EPS + col) = make_float2(f2, f3);
        }
    }
    // reduce partials across the quad (cols within this warp's 64-col slice)
    #pragma unroll
    for (int off = 1; off <= 2; off <<= 1) {
        pa[0][0] += __shfl_xor_sync(0xffffffffu, pa[0][0], off);
        pa[0][1] += __shfl_xor_sync(0xffffffffu, pa[0][1], off);
        pa[1][0] += __shfl_xor_sync(0xffffffffu, pa[1][0], off);
        pa[1][1] += __shfl_xor_sync(0xffffffffu, pa[1][1], off);
    }
    if (t == 0) {
        float* dst = (wc < 2) ? sA1 : sA2;   // wc 0,1 -> fi cols; 2,3 -> fj cols
        atomicAdd(dst + wr * 32 + g,      pa[0][0]);
        atomicAdd(dst + wr * 32 + g + 8,  pa[0][1]);
        atomicAdd(dst + wr * 32 + g + 16, pa[1][0]);
        atomicAdd(dst + wr * 32 + g + 24, pa[1][1]);
    }
    __syncthreads();

    // Final combine: 4 threads per row, 32 cols each.
    {
        const int r = tid >> 2;
        const int grow = block_row + r;
        if (grow < NN) {
            const float A1 = sA1[r] + __ldg(ba1);
            const float A2 = sA2[r] + __ldg(ba2);
            const float att = 1.0f / (1.0f + __expf(-(A1 + A2)));
            if ((tid & 3) == 0) { g_a1[grow] = A1; g_a2[grow] = A2; }
            const int c0 = (tid & 3) * 32;
            float* orow = out  + (size_t)grow * DD;
            float* frow = g_fj + (size_t)grow * DD;
            const float* fi = EP + r * EPS + c0;
            const float* fj = EP + r * EPS + 128 + c0;
            #pragma unroll
            for (int q = 0; q < 8; q++) {
                float4 vi = *(const float4*)(fi + 4 * q);
                float4 vj = *(const float4*)(fj + 4 * q);
                *(float4*)(frow + c0 + 4 * q) = vj;
                *(float4*)(orow + c0 + 4 * q) =
                    make_float4(vi.x + att * vj.x, vi.y + att * vj.y,
                                vi.z + att * vj.z, vi.w + att * vj.w);
            }
        }
    }
}

// ---------------------------------------------------------------------------
// Kernel 2: edge scatter, 4 edges per warp (MLP), red.global.add.v4.
// ---------------------------------------------------------------------------
__global__ __launch_bounds__(256) void gat_edge(const int* __restrict__ ei,
                                                float* __restrict__ out)
{
    const int warp = threadIdx.x >> 5;
    const int lane = threadIdx.x & 31;
    const int e0 = (blockIdx.x * 8 + warp) * 4;

    int r[4], c[4];
    #pragma unroll
    for (int i = 0; i < 4; i++) {
        r[i] = __ldg(ei + e0 + i);
        c[i] = __ldg(ei + EE + e0 + i);
    }
    float s[4];
    #pragma unroll
    for (int i = 0; i < 4; i++) s[i] = g_a1[r[i]] + g_a2[c[i]];

    float4 v[4];
    #pragma unroll
    for (int i = 0; i < 4; i++)
        v[i] = *(const float4*)(g_fj + (size_t)c[i] * DD + lane * 4);

    #pragma unroll
    for (int i = 0; i < 4; i++) {
        float att = 1.0f / (1.0f + __expf(-s[i]));
        float* p = out + (size_t)r[i] * DD + lane * 4;
        asm volatile("red.global.add.v4.f32 [%0], {%1, %2, %3, %4};"
                     :: "l"(p), "f"(att * v[i].x), "f"(att * v[i].y),
                        "f"(att * v[i].z), "f"(att * v[i].w)
                     : "memory");
    }
}

// ---------------------------------------------------------------------------

extern "C" void kernel_launch(void* const* d_in, const int* in_sizes, int n_in,
                              void* d_out, int out_size)
{
    const float* X   = (const float*)d_in[0];
    const float* W1  = (const float*)d_in[1];
    const float* b1  = (const float*)d_in[2];
    const float* W2  = (const float*)d_in[3];
    const float* b2  = (const float*)d_in[4];
    const float* wa1 = (const float*)d_in[5];
    const float* ba1 = (const float*)d_in[6];
    const float* wa2 = (const float*)d_in[7];
    const float* ba2 = (const float*)d_in[8];
    const int*   ei  = (const int*)d_in[9];
    float* out = (float*)d_out;

    cudaFuncSetAttribute(gat_gemm, cudaFuncAttributeMaxDynamicSharedMemorySize,
                         SM_BYTES);

    gat_gemm<<<(NN + 127) / 128, 512, SM_BYTES>>>(X, W1, b1, W2, b2,
                                                  wa1, ba1, wa2, ba2, out);
    gat_edge<<<EE / 32, 256>>>(ei, out);   // 25000 blocks x 8 warps x 4 edges
}